// round 6
// baseline (speedup 1.0000x reference)
#include <cuda_runtime.h>
#include <math.h>

// Problem constants
#define BATCH 2
#define SEQ   2048
#define DIM   1024
#define NH    16
#define HDM   64
#define BSROWS (BATCH*SEQ)   // 4096

// ---------------------------------------------------------------------------
// Scratch (no cudaMalloc allowed) : Q,K,V projections + context
// ---------------------------------------------------------------------------
__device__ float g_q[BSROWS * DIM];
__device__ float g_k[BSROWS * DIM];
__device__ float g_v[BSROWS * DIM];
__device__ float g_ctx[BSROWS * DIM];

// ---------------------------------------------------------------------------
// fp32 tiled GEMM: C[M,N] = scale * (A[M,K] @ B[K,N])   (all row-major)
// BM=BN=128, BK=16, 256 threads, 8x8 micro-tile per thread.
// ---------------------------------------------------------------------------
#define BM 128
#define BN 128
#define BK 16

__global__ __launch_bounds__(256, 2)
void gemm_f32(const float* __restrict__ A, const float* __restrict__ B,
              float* __restrict__ C, int M, int N, int K, float scale) {
    __shared__ float As[BK][BM + 4];   // transposed: As[k][m], pad 132 (mult of 4)
    __shared__ float Bs[BK][BN];       // Bs[k][n]

    const int tid = threadIdx.x;
    const int bx = blockIdx.x;         // N tile
    const int by = blockIdx.y;         // M tile
    const int tr = tid >> 4;           // 0..15 (row group)
    const int tc = tid & 15;           // 0..15 (col group)

    const float* Ab = A + (size_t)by * BM * K;
    const float* Bb = B + (size_t)bx * BN;

    float acc[8][8];
#pragma unroll
    for (int i = 0; i < 8; i++)
#pragma unroll
        for (int j = 0; j < 8; j++) acc[i][j] = 0.f;

    for (int kt = 0; kt < K; kt += BK) {
        // Load A tile (128x16) transposed into As
#pragma unroll
        for (int n = 0; n < 2; n++) {
            int id = tid + n * 256;
            int r  = id >> 2;            // 0..127
            int c4 = (id & 3) * 4;       // 0,4,8,12
            float4 v = *(const float4*)(Ab + (size_t)r * K + kt + c4);
            As[c4 + 0][r] = v.x;
            As[c4 + 1][r] = v.y;
            As[c4 + 2][r] = v.z;
            As[c4 + 3][r] = v.w;
        }
        // Load B tile (16x128) directly
#pragma unroll
        for (int n = 0; n < 2; n++) {
            int id = tid + n * 256;
            int r  = id >> 5;            // 0..15
            int c4 = (id & 31) * 4;      // 0..124
            *(float4*)(&Bs[r][c4]) = *(const float4*)(Bb + (size_t)(kt + r) * N + c4);
        }
        __syncthreads();

#pragma unroll
        for (int k = 0; k < BK; k++) {
            float a[8], b[8];
            *(float4*)(a)     = *(const float4*)(&As[k][tr * 8]);
            *(float4*)(a + 4) = *(const float4*)(&As[k][tr * 8 + 4]);
            *(float4*)(b)     = *(const float4*)(&Bs[k][tc * 8]);
            *(float4*)(b + 4) = *(const float4*)(&Bs[k][tc * 8 + 4]);
#pragma unroll
            for (int i = 0; i < 8; i++)
#pragma unroll
                for (int j = 0; j < 8; j++)
                    acc[i][j] += a[i] * b[j];
        }
        __syncthreads();
    }

    // Epilogue
#pragma unroll
    for (int i = 0; i < 8; i++) {
        int row = by * BM + tr * 8 + i;
        float* Crow = C + (size_t)row * N + bx * BN + tc * 8;
#pragma unroll
        for (int j4 = 0; j4 < 8; j4 += 4) {
            float4 r;
            r.x = acc[i][j4 + 0] * scale;
            r.y = acc[i][j4 + 1] * scale;
            r.z = acc[i][j4 + 2] * scale;
            r.w = acc[i][j4 + 3] * scale;
            *(float4*)(Crow + j4) = r;
        }
    }
}

// ---------------------------------------------------------------------------
// Flash attention: one block per (b, h, q-tile of 64 rows).
// Br=Bc=64, HD=64. 256 threads as 16x16; each thread owns a 4x4 micro-tile.
// smem (dynamic, ~68KB): Qs[d][i], Ks[d][j], Vs[j][c], Ps[j][i], stride 68.
// ---------------------------------------------------------------------------
#define ALD 68   // padded leading dim (multiple of 4 for float4 alignment)

__global__ __launch_bounds__(256)
void attn_kernel(const float* __restrict__ Q, const float* __restrict__ K,
                 const float* __restrict__ V, float* __restrict__ O) {
    extern __shared__ float sm[];
    float* Qs = sm;                 // [64][ALD]  Qs[d*ALD + i] = Q[i][d]
    float* Ks = Qs + 64 * ALD;      // Ks[d*ALD + j] = K[j][d]
    float* Vs = Ks + 64 * ALD;      // Vs[j*ALD + c] = V[j][c]
    float* Ps = Vs + 64 * ALD;      // Ps[j*ALD + i] = P[i][j]

    const int b  = blockIdx.z;
    const int h  = blockIdx.y;
    const int qt = blockIdx.x;
    const int tid = threadIdx.x;
    const int ty = tid >> 4;        // 0..15  -> rows ty*4..ty*4+3
    const int tx = tid & 15;        // 0..15  -> cols tx*4..tx*4+3

    const float* Qg = Q + ((size_t)b * SEQ + qt * 64) * DIM + h * HDM;

    // Load Q tile transposed
#pragma unroll
    for (int n = 0; n < 4; n++) {
        int id = tid + n * 256;
        int i  = id >> 4;           // 0..63
        int d4 = (id & 15) * 4;     // 0..60
        float4 v = *(const float4*)(Qg + (size_t)i * DIM + d4);
        Qs[(d4 + 0) * ALD + i] = v.x;
        Qs[(d4 + 1) * ALD + i] = v.y;
        Qs[(d4 + 2) * ALD + i] = v.z;
        Qs[(d4 + 3) * ALD + i] = v.w;
    }

    float m[4], l[4], o[4][4];
#pragma unroll
    for (int a = 0; a < 4; a++) {
        m[a] = -INFINITY;
        l[a] = 0.f;
#pragma unroll
        for (int c = 0; c < 4; c++) o[a][c] = 0.f;
    }

    for (int kt = 0; kt < SEQ / 64; kt++) {
        const float* Kg = K + ((size_t)b * SEQ + kt * 64) * DIM + h * HDM;
        const float* Vg = V + ((size_t)b * SEQ + kt * 64) * DIM + h * HDM;
        // Load K (transposed) and V (natural)
#pragma unroll
        for (int n = 0; n < 4; n++) {
            int id = tid + n * 256;
            int j  = id >> 4;
            int d4 = (id & 15) * 4;
            float4 kv = *(const float4*)(Kg + (size_t)j * DIM + d4);
            Ks[(d4 + 0) * ALD + j] = kv.x;
            Ks[(d4 + 1) * ALD + j] = kv.y;
            Ks[(d4 + 2) * ALD + j] = kv.z;
            Ks[(d4 + 3) * ALD + j] = kv.w;
            float4 vv = *(const float4*)(Vg + (size_t)j * DIM + d4);
            *(float4*)(&Vs[j * ALD + d4]) = vv;
        }
        __syncthreads();

        // S = Q K^T  (4x4 per thread over k=0..63)
        float s[4][4];
#pragma unroll
        for (int a = 0; a < 4; a++)
#pragma unroll
            for (int c = 0; c < 4; c++) s[a][c] = 0.f;

#pragma unroll 8
        for (int k = 0; k < 64; k++) {
            float4 qa = *(const float4*)(&Qs[k * ALD + ty * 4]);
            float4 kb = *(const float4*)(&Ks[k * ALD + tx * 4]);
            float aq[4] = {qa.x, qa.y, qa.z, qa.w};
            float bk[4] = {kb.x, kb.y, kb.z, kb.w};
#pragma unroll
            for (int a = 0; a < 4; a++)
#pragma unroll
                for (int c = 0; c < 4; c++)
                    s[a][c] += aq[a] * bk[c];
        }

        // Online softmax per row (16 threads with same ty share a row;
        // they are one half-warp -> shfl_xor over offsets 8,4,2,1).
#pragma unroll
        for (int a = 0; a < 4; a++) {
            float mloc = fmaxf(fmaxf(s[a][0], s[a][1]), fmaxf(s[a][2], s[a][3]));
#pragma unroll
            for (int off = 8; off >= 1; off >>= 1)
                mloc = fmaxf(mloc, __shfl_xor_sync(0xffffffffu, mloc, off));
            float mn = fmaxf(m[a], mloc);
            float alpha = __expf(m[a] - mn);
            float p0 = __expf(s[a][0] - mn);
            float p1 = __expf(s[a][1] - mn);
            float p2 = __expf(s[a][2] - mn);
            float p3 = __expf(s[a][3] - mn);
            float sum = p0 + p1 + p2 + p3;
#pragma unroll
            for (int off = 8; off >= 1; off >>= 1)
                sum += __shfl_xor_sync(0xffffffffu, sum, off);
            l[a] = l[a] * alpha + sum;
            m[a] = mn;
#pragma unroll
            for (int c = 0; c < 4; c++) o[a][c] *= alpha;
            int i = ty * 4 + a;
            Ps[(tx * 4 + 0) * ALD + i] = p0;
            Ps[(tx * 4 + 1) * ALD + i] = p1;
            Ps[(tx * 4 + 2) * ALD + i] = p2;
            Ps[(tx * 4 + 3) * ALD + i] = p3;
        }
        __syncthreads();

        // O += P V  (4x4 per thread over j=0..63)
#pragma unroll 8
        for (int j = 0; j < 64; j++) {
            float4 pa = *(const float4*)(&Ps[j * ALD + ty * 4]);
            float4 vb = *(const float4*)(&Vs[j * ALD + tx * 4]);
            float ap[4] = {pa.x, pa.y, pa.z, pa.w};
            float bv[4] = {vb.x, vb.y, vb.z, vb.w};
#pragma unroll
            for (int a = 0; a < 4; a++)
#pragma unroll
                for (int c = 0; c < 4; c++)
                    o[a][c] += ap[a] * bv[c];
        }
        __syncthreads();
    }

    // Epilogue: normalize, write ctx in [B,S,D] layout (head h -> cols h*64..)
    float* Og = O + ((size_t)b * SEQ + qt * 64) * DIM + h * HDM;
#pragma unroll
    for (int a = 0; a < 4; a++) {
        float inv = 1.f / l[a];
        float4 r;
        r.x = o[a][0] * inv;
        r.y = o[a][1] * inv;
        r.z = o[a][2] * inv;
        r.w = o[a][3] * inv;
        *(float4*)(Og + (size_t)(ty * 4 + a) * DIM + tx * 4) = r;
    }
}

// ---------------------------------------------------------------------------
// Launch
// ---------------------------------------------------------------------------
extern "C" void kernel_launch(void* const* d_in, const int* in_sizes, int n_in,
                              void* d_out, int out_size) {
    const float* queries = (const float*)d_in[0];
    const float* keysin  = (const float*)d_in[1];
    const float* valsin  = (const float*)d_in[2];
    const float* Wq      = (const float*)d_in[3];
    const float* Wk      = (const float*)d_in[4];
    const float* Wv      = (const float*)d_in[5];
    const float* Wo      = (const float*)d_in[6];
    float* out = (float*)d_out;

    float *gq, *gk, *gv, *gctx;
    cudaGetSymbolAddress((void**)&gq,   g_q);
    cudaGetSymbolAddress((void**)&gk,   g_k);
    cudaGetSymbolAddress((void**)&gv,   g_v);
    cudaGetSymbolAddress((void**)&gctx, g_ctx);

    const int attn_smem = 4 * 64 * ALD * (int)sizeof(float);  // 69632 B
    cudaFuncSetAttribute(attn_kernel,
                         cudaFuncAttributeMaxDynamicSharedMemorySize, attn_smem);

    dim3 gemm_grid(DIM / BN, BSROWS / BM);   // (8, 32)
    const float qscale = 1.0f / 8.0f;        // HD^-0.5, HD=64

    gemm_f32<<<gemm_grid, 256>>>(queries, Wq, gq, BSROWS, DIM, DIM, qscale);
    gemm_f32<<<gemm_grid, 256>>>(keysin,  Wk, gk, BSROWS, DIM, DIM, 1.0f);
    gemm_f32<<<gemm_grid, 256>>>(valsin,  Wv, gv, BSROWS, DIM, DIM, 1.0f);

    dim3 attn_grid(SEQ / 64, NH, BATCH);     // (32, 16, 2)
    attn_kernel<<<attn_grid, 256, attn_smem>>>(gq, gk, gv, gctx);

    gemm_f32<<<gemm_grid, 256>>>(gctx, Wo, out, BSROWS, DIM, DIM, 1.0f);
}

// round 10
// speedup vs baseline: 1.3593x; 1.3593x over previous
#include <cuda_runtime.h>
#include <cuda_bf16.h>
#include <math.h>
#include <stdint.h>

// Problem constants
#define BATCH 2
#define SEQ   2048
#define DIM   1024
#define NH    16
#define HDM   64
#define BSROWS (BATCH*SEQ)   // 4096

// ---------------------------------------------------------------------------
// Scratch (no cudaMalloc allowed)
// ---------------------------------------------------------------------------
__device__ float g_q[BSROWS * DIM];
__device__ float g_k[BSROWS * DIM];
__device__ float g_v[BSROWS * DIM];
__device__ float g_ctx[BSROWS * DIM];
// Transposed + hi/lo-split weights: [4][N=1024][K=1024] bf16
__device__ __nv_bfloat16 g_wth[4u * DIM * DIM];
__device__ __nv_bfloat16 g_wtl[4u * DIM * DIM];

// ---------------------------------------------------------------------------
// Helpers
// ---------------------------------------------------------------------------
__device__ __forceinline__ uint32_t smem_u32(const void* p) {
    uint32_t a;
    asm("{ .reg .u64 t; cvta.to.shared.u64 t, %1; cvt.u32.u64 %0, t; }"
        : "=r"(a) : "l"(p));
    return a;
}

__device__ __forceinline__ void ldsm_x4(uint32_t* r, uint32_t addr) {
    asm volatile("ldmatrix.sync.aligned.m8n8.x4.shared.b16 {%0,%1,%2,%3}, [%4];"
                 : "=r"(r[0]), "=r"(r[1]), "=r"(r[2]), "=r"(r[3]) : "r"(addr));
}

__device__ __forceinline__ void mma_bf16(float* d, const uint32_t* a, const uint32_t* b) {
    asm volatile(
        "mma.sync.aligned.m16n8k16.row.col.f32.bf16.bf16.f32 "
        "{%0,%1,%2,%3}, {%4,%5,%6,%7}, {%8,%9}, {%0,%1,%2,%3};"
        : "+f"(d[0]), "+f"(d[1]), "+f"(d[2]), "+f"(d[3])
        : "r"(a[0]), "r"(a[1]), "r"(a[2]), "r"(a[3]), "r"(b[0]), "r"(b[1]));
}

// ---------------------------------------------------------------------------
// Weight prep: transpose + hi/lo bf16 split. W[K][N] fp32 -> Wt[N][K] bf16 x2
// grid (32, 32, 4), block 256 (32x8)
// ---------------------------------------------------------------------------
__global__ void split_weights(const float* __restrict__ W0, const float* __restrict__ W1,
                              const float* __restrict__ W2, const float* __restrict__ W3) {
    const float* W = blockIdx.z == 0 ? W0 : blockIdx.z == 1 ? W1
                   : blockIdx.z == 2 ? W2 : W3;
    __nv_bfloat16* oh = g_wth + (size_t)blockIdx.z * DIM * DIM;
    __nv_bfloat16* ol = g_wtl + (size_t)blockIdx.z * DIM * DIM;

    __shared__ float t[32][33];
    const int k0 = blockIdx.x * 32, n0 = blockIdx.y * 32;
    const int tx = threadIdx.x & 31, ty = threadIdx.x >> 5;

#pragma unroll
    for (int i = 0; i < 32; i += 8)
        t[ty + i][tx] = W[(size_t)(k0 + ty + i) * DIM + n0 + tx];
    __syncthreads();
#pragma unroll
    for (int i = 0; i < 32; i += 8) {
        float v = t[tx][ty + i];
        __nv_bfloat16 h = __float2bfloat16(v);
        __nv_bfloat16 l = __float2bfloat16(v - __bfloat162float(h));
        oh[(size_t)(n0 + ty + i) * DIM + k0 + tx] = h;
        ol[(size_t)(n0 + ty + i) * DIM + k0 + tx] = l;
    }
}

// ---------------------------------------------------------------------------
// mma.sync split-bf16 GEMM: C[M,1024] = scale * A[M,1024] @ Bt^T
//   Bt given as [N=1024][K=1024] bf16 (hi, lo). A fp32, split in-flight.
//   Block tile 128x128, BK=32. 256 threads = 8 warps as 2(M) x 4(N).
//   Warp tile 64x32 -> 4 m-frags x 4 n-frags of m16n8k16.
//   C = Ah@Bh + Ah@Bl + Al@Bh  (lo*lo dropped)
// ---------------------------------------------------------------------------
#define TLD 40   // smem tile leading dim in bf16 elems (80B rows, ldmatrix conflict-free)

__global__ __launch_bounds__(256)
void gemm_mma(const float* __restrict__ A, const __nv_bfloat16* __restrict__ Bh,
              const __nv_bfloat16* __restrict__ Bl, float* __restrict__ C,
              float scale) {
    __shared__ __nv_bfloat16 sAh[128 * TLD];
    __shared__ __nv_bfloat16 sAl[128 * TLD];
    __shared__ __nv_bfloat16 sBh[128 * TLD];
    __shared__ __nv_bfloat16 sBl[128 * TLD];

    const int tid = threadIdx.x;
    const int wid = tid >> 5, lane = tid & 31;
    const int wm = wid >> 2;          // 0..1  (M warp row)
    const int wn = wid & 3;           // 0..3  (N warp col)
    const int bx = blockIdx.x, by = blockIdx.y;

    const float*         Ab  = A  + (size_t)(by * 128) * DIM;
    const __nv_bfloat16* Bhb = Bh + (size_t)(bx * 128) * DIM;
    const __nv_bfloat16* Blb = Bl + (size_t)(bx * 128) * DIM;

    const uint32_t aAh = smem_u32(sAh), aAl = smem_u32(sAl);
    const uint32_t aBh = smem_u32(sBh), aBl = smem_u32(sBl);

    // ldmatrix lane-address components (in elements)
    const int a_row = (lane & 15);            // + wm*64 + mf*16
    const int a_col = (lane >> 4) * 8;        // + ks*16
    const int b_row = ((lane >> 4) << 3) + (lane & 7);  // + wn*32 + j*16
    const int b_col = ((lane >> 3) & 1) * 8;            // + ks*16

    float acc[4][4][4];
#pragma unroll
    for (int mf = 0; mf < 4; mf++)
#pragma unroll
        for (int nf = 0; nf < 4; nf++)
#pragma unroll
            for (int e = 0; e < 4; e++) acc[mf][nf][e] = 0.f;

    for (int kt = 0; kt < DIM / 32; kt++) {
        if (kt > 0) __syncthreads();   // protect previous iter's reads

        // A tile 128x32 fp32 -> hi/lo bf16
#pragma unroll
        for (int p = 0; p < 4; p++) {
            int id = tid + p * 256;
            int r = id >> 3, c = (id & 7) * 4;
            float4 v = *(const float4*)(Ab + (size_t)r * DIM + kt * 32 + c);
            __nv_bfloat16 h0 = __float2bfloat16(v.x);
            __nv_bfloat16 h1 = __float2bfloat16(v.y);
            __nv_bfloat16 h2 = __float2bfloat16(v.z);
            __nv_bfloat16 h3 = __float2bfloat16(v.w);
            __nv_bfloat16 l0 = __float2bfloat16(v.x - __bfloat162float(h0));
            __nv_bfloat16 l1 = __float2bfloat16(v.y - __bfloat162float(h1));
            __nv_bfloat16 l2 = __float2bfloat16(v.z - __bfloat162float(h2));
            __nv_bfloat16 l3 = __float2bfloat16(v.w - __bfloat162float(h3));
            ushort4 hp = make_ushort4(*(unsigned short*)&h0, *(unsigned short*)&h1,
                                      *(unsigned short*)&h2, *(unsigned short*)&h3);
            ushort4 lp = make_ushort4(*(unsigned short*)&l0, *(unsigned short*)&l1,
                                      *(unsigned short*)&l2, *(unsigned short*)&l3);
            *(ushort4*)(&sAh[r * TLD + c]) = hp;
            *(ushort4*)(&sAl[r * TLD + c]) = lp;
        }
        // B tiles 128x32 bf16 (row-major [N][K])
#pragma unroll
        for (int p = 0; p < 2; p++) {
            int id = tid + p * 256;
            int n = id >> 2, c = (id & 3) * 8;
            *(float4*)(&sBh[n * TLD + c]) =
                *(const float4*)(Bhb + (size_t)n * DIM + kt * 32 + c);
            *(float4*)(&sBl[n * TLD + c]) =
                *(const float4*)(Blb + (size_t)n * DIM + kt * 32 + c);
        }
        __syncthreads();

#pragma unroll
        for (int ks = 0; ks < 2; ks++) {
            uint32_t ah[4][4], al[4][4], bh[4][2], bl[4][2];
#pragma unroll
            for (int mf = 0; mf < 4; mf++) {
                uint32_t off = (uint32_t)((wm * 64 + mf * 16 + a_row) * TLD
                                          + ks * 16 + a_col) * 2;
                ldsm_x4(ah[mf], aAh + off);
                ldsm_x4(al[mf], aAl + off);
            }
#pragma unroll
            for (int j = 0; j < 2; j++) {   // each x4 covers 2 n-frags
                uint32_t off = (uint32_t)((wn * 32 + j * 16 + b_row) * TLD
                                          + ks * 16 + b_col) * 2;
                uint32_t rh[4], rl[4];
                ldsm_x4(rh, aBh + off);
                ldsm_x4(rl, aBl + off);
                bh[j * 2][0] = rh[0]; bh[j * 2][1] = rh[1];
                bh[j * 2 + 1][0] = rh[2]; bh[j * 2 + 1][1] = rh[3];
                bl[j * 2][0] = rl[0]; bl[j * 2][1] = rl[1];
                bl[j * 2 + 1][0] = rl[2]; bl[j * 2 + 1][1] = rl[3];
            }
#pragma unroll
            for (int mf = 0; mf < 4; mf++)
#pragma unroll
                for (int nf = 0; nf < 4; nf++) {
                    mma_bf16(acc[mf][nf], ah[mf], bh[nf]);
                    mma_bf16(acc[mf][nf], ah[mf], bl[nf]);
                    mma_bf16(acc[mf][nf], al[mf], bh[nf]);
                }
        }
    }

    // Epilogue: c-frag thread mapping: rows t/4 and t/4+8, cols (t%4)*2..+1
    const int er = lane >> 2, ec = (lane & 3) * 2;
#pragma unroll
    for (int mf = 0; mf < 4; mf++) {
        int row0 = by * 128 + wm * 64 + mf * 16 + er;
#pragma unroll
        for (int nf = 0; nf < 4; nf++) {
            int col = bx * 128 + wn * 32 + nf * 8 + ec;
            float2 v0 = make_float2(acc[mf][nf][0] * scale, acc[mf][nf][1] * scale);
            float2 v1 = make_float2(acc[mf][nf][2] * scale, acc[mf][nf][3] * scale);
            *(float2*)(C + (size_t)row0 * DIM + col) = v0;
            *(float2*)(C + (size_t)(row0 + 8) * DIM + col) = v1;
        }
    }
}

// ---------------------------------------------------------------------------
// Flash attention (unchanged fp32): one block per (b, h, q-tile of 64 rows).
// ---------------------------------------------------------------------------
#define ALD 68

__global__ __launch_bounds__(256)
void attn_kernel(const float* __restrict__ Q, const float* __restrict__ K,
                 const float* __restrict__ V, float* __restrict__ O) {
    extern __shared__ float smf[];
    float* Qs = smf;
    float* Ks = Qs + 64 * ALD;
    float* Vs = Ks + 64 * ALD;
    float* Ps = Vs + 64 * ALD;

    const int b  = blockIdx.z;
    const int h  = blockIdx.y;
    const int qt = blockIdx.x;
    const int tid = threadIdx.x;
    const int ty = tid >> 4;
    const int tx = tid & 15;

    const float* Qg = Q + ((size_t)b * SEQ + qt * 64) * DIM + h * HDM;

#pragma unroll
    for (int n = 0; n < 4; n++) {
        int id = tid + n * 256;
        int i  = id >> 4;
        int d4 = (id & 15) * 4;
        float4 v = *(const float4*)(Qg + (size_t)i * DIM + d4);
        Qs[(d4 + 0) * ALD + i] = v.x;
        Qs[(d4 + 1) * ALD + i] = v.y;
        Qs[(d4 + 2) * ALD + i] = v.z;
        Qs[(d4 + 3) * ALD + i] = v.w;
    }

    float m[4], l[4], o[4][4];
#pragma unroll
    for (int a = 0; a < 4; a++) {
        m[a] = -INFINITY;
        l[a] = 0.f;
#pragma unroll
        for (int c = 0; c < 4; c++) o[a][c] = 0.f;
    }

    for (int kt = 0; kt < SEQ / 64; kt++) {
        const float* Kg = K + ((size_t)b * SEQ + kt * 64) * DIM + h * HDM;
        const float* Vg = V + ((size_t)b * SEQ + kt * 64) * DIM + h * HDM;
#pragma unroll
        for (int n = 0; n < 4; n++) {
            int id = tid + n * 256;
            int j  = id >> 4;
            int d4 = (id & 15) * 4;
            float4 kv = *(const float4*)(Kg + (size_t)j * DIM + d4);
            Ks[(d4 + 0) * ALD + j] = kv.x;
            Ks[(d4 + 1) * ALD + j] = kv.y;
            Ks[(d4 + 2) * ALD + j] = kv.z;
            Ks[(d4 + 3) * ALD + j] = kv.w;
            float4 vv = *(const float4*)(Vg + (size_t)j * DIM + d4);
            *(float4*)(&Vs[j * ALD + d4]) = vv;
        }
        __syncthreads();

        float s[4][4];
#pragma unroll
        for (int a = 0; a < 4; a++)
#pragma unroll
            for (int c = 0; c < 4; c++) s[a][c] = 0.f;

#pragma unroll 8
        for (int k = 0; k < 64; k++) {
            float4 qa = *(const float4*)(&Qs[k * ALD + ty * 4]);
            float4 kb = *(const float4*)(&Ks[k * ALD + tx * 4]);
            float aq[4] = {qa.x, qa.y, qa.z, qa.w};
            float bk[4] = {kb.x, kb.y, kb.z, kb.w};
#pragma unroll
            for (int a = 0; a < 4; a++)
#pragma unroll
                for (int c = 0; c < 4; c++)
                    s[a][c] += aq[a] * bk[c];
        }

#pragma unroll
        for (int a = 0; a < 4; a++) {
            float mloc = fmaxf(fmaxf(s[a][0], s[a][1]), fmaxf(s[a][2], s[a][3]));
#pragma unroll
            for (int off = 8; off >= 1; off >>= 1)
                mloc = fmaxf(mloc, __shfl_xor_sync(0xffffffffu, mloc, off));
            float mn = fmaxf(m[a], mloc);
            float alpha = __expf(m[a] - mn);
            float p0 = __expf(s[a][0] - mn);
            float p1 = __expf(s[a][1] - mn);
            float p2 = __expf(s[a][2] - mn);
            float p3 = __expf(s[a][3] - mn);
            float sum = p0 + p1 + p2 + p3;
#pragma unroll
            for (int off = 8; off >= 1; off >>= 1)
                sum += __shfl_xor_sync(0xffffffffu, sum, off);
            l[a] = l[a] * alpha + sum;
            m[a] = mn;
#pragma unroll
            for (int c = 0; c < 4; c++) o[a][c] *= alpha;
            int i = ty * 4 + a;
            Ps[(tx * 4 + 0) * ALD + i] = p0;
            Ps[(tx * 4 + 1) * ALD + i] = p1;
            Ps[(tx * 4 + 2) * ALD + i] = p2;
            Ps[(tx * 4 + 3) * ALD + i] = p3;
        }
        __syncthreads();

#pragma unroll 8
        for (int j = 0; j < 64; j++) {
            float4 pa = *(const float4*)(&Ps[j * ALD + ty * 4]);
            float4 vb = *(const float4*)(&Vs[j * ALD + tx * 4]);
            float ap[4] = {pa.x, pa.y, pa.z, pa.w};
            float bv[4] = {vb.x, vb.y, vb.z, vb.w};
#pragma unroll
            for (int a = 0; a < 4; a++)
#pragma unroll
                for (int c = 0; c < 4; c++)
                    o[a][c] += ap[a] * bv[c];
        }
        __syncthreads();
    }

    float* Og = O + ((size_t)b * SEQ + qt * 64) * DIM + h * HDM;
#pragma unroll
    for (int a = 0; a < 4; a++) {
        float inv = 1.f / l[a];
        float4 r;
        r.x = o[a][0] * inv;
        r.y = o[a][1] * inv;
        r.z = o[a][2] * inv;
        r.w = o[a][3] * inv;
        *(float4*)(Og + (size_t)(ty * 4 + a) * DIM + tx * 4) = r;
    }
}

// ---------------------------------------------------------------------------
// Launch
// ---------------------------------------------------------------------------
extern "C" void kernel_launch(void* const* d_in, const int* in_sizes, int n_in,
                              void* d_out, int out_size) {
    const float* queries = (const float*)d_in[0];
    const float* keysin  = (const float*)d_in[1];
    const float* valsin  = (const float*)d_in[2];
    const float* Wq      = (const float*)d_in[3];
    const float* Wk      = (const float*)d_in[4];
    const float* Wv      = (const float*)d_in[5];
    const float* Wo      = (const float*)d_in[6];
    float* out = (float*)d_out;

    float *gq, *gk, *gv, *gctx;
    __nv_bfloat16 *wth, *wtl;
    cudaGetSymbolAddress((void**)&gq,   g_q);
    cudaGetSymbolAddress((void**)&gk,   g_k);
    cudaGetSymbolAddress((void**)&gv,   g_v);
    cudaGetSymbolAddress((void**)&gctx, g_ctx);
    cudaGetSymbolAddress((void**)&wth,  g_wth);
    cudaGetSymbolAddress((void**)&wtl,  g_wtl);

    const int attn_smem = 4 * 64 * ALD * (int)sizeof(float);  // 69632 B
    cudaFuncSetAttribute(attn_kernel,
                         cudaFuncAttributeMaxDynamicSharedMemorySize, attn_smem);

    // Prep: transpose + split all 4 weights into bf16 hi/lo [N][K]
    split_weights<<<dim3(DIM / 32, DIM / 32, 4), 256>>>(Wq, Wk, Wv, Wo);

    dim3 gg(DIM / 128, BSROWS / 128);      // (8, 32)
    const size_t WSZ = (size_t)DIM * DIM;
    const float qscale = 1.0f / 8.0f;      // HD^-0.5, HD=64

    gemm_mma<<<gg, 256>>>(queries, wth + 0 * WSZ, wtl + 0 * WSZ, gq, qscale);
    gemm_mma<<<gg, 256>>>(keysin,  wth + 1 * WSZ, wtl + 1 * WSZ, gk, 1.0f);
    gemm_mma<<<gg, 256>>>(valsin,  wth + 2 * WSZ, wtl + 2 * WSZ, gv, 1.0f);

    dim3 attn_grid(SEQ / 64, NH, BATCH);   // (32, 16, 2)
    attn_kernel<<<attn_grid, 256, attn_smem>>>(gq, gk, gv, gctx);

    gemm_mma<<<gg, 256>>>(gctx, wth + 3 * WSZ, wtl + 3 * WSZ, out, 1.0f);
}